// round 1
// baseline (speedup 1.0000x reference)
#include <cuda_runtime.h>
#include <math.h>

#define NBATCH 192
#define NTOK   256
#define CDIM   256
#define NH     8
#define HD     32
#define NWIN   64
#define QKVD   768   // 3*C

// ---------------- scratch (static __device__, no runtime alloc) ----------------
__device__ float g_qkv [NBATCH * NTOK * QKVD];   // (B, N, 3*H*hd)  ~151 MB
__device__ float g_bias[NH * NTOK * NTOK];       // (H, N, N)        2 MB
__device__ float g_att [NBATCH * NTOK * CDIM];   // attention output pre-proj

// ---------------- rel-pos bias gather: bias[h][n][m] = table[idx[n*m]][h] ------
__global__ void bias_kernel(const float* __restrict__ table,
                            const int*   __restrict__ ridx) {
    int nm = blockIdx.x * blockDim.x + threadIdx.x;
    if (nm >= NTOK * NTOK) return;
    int ri = ridx[nm];
    #pragma unroll
    for (int h = 0; h < NH; h++)
        g_bias[h * NTOK * NTOK + nm] = table[ri * NH + h];
}

// ---------------- NT GEMM: C[m][n] = sum_k A[m][k]*B[n][k] + bias[n] -----------
// A: (M,K) row-major, B: (N,K) row-major (k contiguous both), exact tiles.
template<int BM, int BN, int BK>
__global__ __launch_bounds__(256)
void gemm_nt(const float* __restrict__ A, const float* __restrict__ Bm,
             const float* __restrict__ bias, float* __restrict__ C,
             int M, int Nn, int K)
{
    __shared__ float As [BM][BK + 1];   // row-major, scalar reads (broadcast, cf-free)
    __shared__ float BsT[BK][BN + 4];   // transposed, float4 reads (cf-free, 16B aligned)

    const int tid = threadIdx.x;
    const int tx4 = (tid & 15) * 4;     // col micro-offset
    const int ty4 = (tid >> 4) * 4;     // row micro-offset
    const int row0 = blockIdx.y * BM, col0 = blockIdx.x * BN;

    float acc[8][8] = {};

    for (int k0 = 0; k0 < K; k0 += BK) {
        #pragma unroll
        for (int i = tid; i < BM * BK; i += 256) {
            int r = i / BK, c = i % BK;
            As[r][c] = A[(size_t)(row0 + r) * K + (k0 + c)];
        }
        #pragma unroll
        for (int i = tid; i < BN * BK; i += 256) {
            int r = i / BK, c = i % BK;          // r = n, c = k
            BsT[c][r] = Bm[(size_t)(col0 + r) * K + (k0 + c)];
        }
        __syncthreads();

        #pragma unroll
        for (int k = 0; k < BK; k++) {
            float a[8], b[8];
            #pragma unroll
            for (int i = 0; i < 4; i++) {
                a[i]     = As[ty4 + i][k];
                a[4 + i] = As[64 + ty4 + i][k];
            }
            float4 b0 = *(const float4*)&BsT[k][tx4];
            float4 b1 = *(const float4*)&BsT[k][64 + tx4];
            b[0]=b0.x; b[1]=b0.y; b[2]=b0.z; b[3]=b0.w;
            b[4]=b1.x; b[5]=b1.y; b[6]=b1.z; b[7]=b1.w;
            #pragma unroll
            for (int i = 0; i < 8; i++)
                #pragma unroll
                for (int j = 0; j < 8; j++)
                    acc[i][j] = fmaf(a[i], b[j], acc[i][j]);
        }
        __syncthreads();
    }

    #pragma unroll
    for (int i = 0; i < 8; i++) {
        int r = row0 + ((i < 4) ? (ty4 + i) : (64 + ty4 + (i - 4)));
        #pragma unroll
        for (int j = 0; j < 8; j++) {
            int c = col0 + ((j < 4) ? (tx4 + j) : (64 + tx4 + (j - 4)));
            C[(size_t)r * Nn + c] = acc[i][j] + bias[c];
        }
    }
}

// ---------------- flash attention: 1 CTA per (b,h), 1 thread per query row -----
__global__ __launch_bounds__(256)
void attn_kernel(const float* __restrict__ mask)
{
    extern __shared__ float sm[];            // k_s[256*32] | v_s[256*32] = 64 KB
    float* k_s = sm;
    float* v_s = sm + NTOK * HD;

    const int bh = blockIdx.x;
    const int b  = bh >> 3;
    const int h  = bh & 7;
    const int n  = threadIdx.x;

    const float* qkv_b_ = g_qkv + (size_t)b * NTOK * QKVD;

    // stage K and V for this (b,h): coalesced 128B rows
    for (int i = threadIdx.x; i < NTOK * HD; i += 256) {
        int m = i >> 5, d = i & 31;
        k_s[i] = qkv_b_[m * QKVD + 256 + h * 32 + d];
        v_s[i] = qkv_b_[m * QKVD + 512 + h * 32 + d];
    }
    __syncthreads();

    const float scale = 0.17677669529663687f;   // 32^-0.5
    float q[HD];
    const float* qp = qkv_b_ + n * QKVD + h * 32;
    #pragma unroll
    for (int d = 0; d < HD; d++) q[d] = qp[d] * scale;

    const float* bias_r = g_bias + ((size_t)h * NTOK + n) * NTOK;
    const float* mask_r = mask + ((size_t)(b & 63) * NTOK + n) * NTOK;

    float mmax = -1e30f, lsum = 0.0f;
    float acc[HD] = {};

    for (int m = 0; m < NTOK; m++) {
        const float4* kp = (const float4*)(k_s + m * HD);
        float s = 0.0f;
        #pragma unroll
        for (int d4 = 0; d4 < 8; d4++) {
            float4 kv = kp[d4];
            s = fmaf(q[d4*4+0], kv.x, s);
            s = fmaf(q[d4*4+1], kv.y, s);
            s = fmaf(q[d4*4+2], kv.z, s);
            s = fmaf(q[d4*4+3], kv.w, s);
        }
        s += bias_r[m] + mask_r[m];

        if (s > mmax) {                          // rare after first few iters
            float cor = __expf(mmax - s);
            lsum *= cor;
            #pragma unroll
            for (int d = 0; d < HD; d++) acc[d] *= cor;
            mmax = s;
        }
        float p = __expf(s - mmax);
        lsum += p;

        const float4* vp = (const float4*)(v_s + m * HD);
        #pragma unroll
        for (int d4 = 0; d4 < 8; d4++) {
            float4 vv = vp[d4];
            acc[d4*4+0] = fmaf(p, vv.x, acc[d4*4+0]);
            acc[d4*4+1] = fmaf(p, vv.y, acc[d4*4+1]);
            acc[d4*4+2] = fmaf(p, vv.z, acc[d4*4+2]);
            acc[d4*4+3] = fmaf(p, vv.w, acc[d4*4+3]);
        }
    }

    float inv = 1.0f / lsum;
    float* op = g_att + ((size_t)b * NTOK + n) * CDIM + h * 32;
    #pragma unroll
    for (int d = 0; d < HD; d++) op[d] = acc[d] * inv;
}

// --------------------------------------------------------------------------
extern "C" void kernel_launch(void* const* d_in, const int* in_sizes, int n_in,
                              void* d_out, int out_size)
{
    const float* x      = (const float*)d_in[0];
    const float* mask   = (const float*)d_in[1];
    const float* qkv_w  = (const float*)d_in[2];
    const float* qkv_b  = (const float*)d_in[3];
    const float* proj_w = (const float*)d_in[4];
    const float* proj_b = (const float*)d_in[5];
    const float* table  = (const float*)d_in[6];
    const int*   ridx   = (const int*)d_in[7];
    float* out = (float*)d_out;

    float *qkv_ptr = nullptr, *att_ptr = nullptr;
    cudaGetSymbolAddress((void**)&qkv_ptr, g_qkv);
    cudaGetSymbolAddress((void**)&att_ptr, g_att);

    // 1) rel-pos bias gather (H,N,N)
    bias_kernel<<<(NTOK * NTOK + 255) / 256, 256>>>(table, ridx);

    // 2) QKV projection: (49152,256) x (768,256)^T -> (49152,768)
    gemm_nt<128,128,16><<<dim3(QKVD / 128, (NBATCH * NTOK) / 128), 256>>>(
        x, qkv_w, qkv_b, qkv_ptr, NBATCH * NTOK, QKVD, CDIM);

    // 3) window attention (flash-style), 64 KB dynamic smem
    cudaFuncSetAttribute(attn_kernel,
                         cudaFuncAttributeMaxDynamicSharedMemorySize, 65536);
    attn_kernel<<<NBATCH * NH, 256, 65536>>>(mask);

    // 4) output projection: (49152,256) x (256,256)^T -> d_out
    gemm_nt<128,128,16><<<dim3(CDIM / 128, (NBATCH * NTOK) / 128), 256>>>(
        att_ptr, proj_w, proj_b, out, NBATCH * NTOK, CDIM, CDIM);
}

// round 2
// speedup vs baseline: 1.4377x; 1.4377x over previous
#include <cuda_runtime.h>
#include <math.h>
#include <stdint.h>

#define NBATCH 192
#define NTOK   256
#define CDIM   256
#define NH     8
#define HD     32
#define QKVD   768   // 3*C

// ---------------- scratch (static __device__, no runtime alloc) ----------------
__device__ float g_qkv [NBATCH * NTOK * QKVD];   // (B, N, 3*H*hd)
__device__ float g_bias[NH * NTOK * NTOK];       // (H, N, N)
__device__ float g_att [NBATCH * NTOK * CDIM];   // attention output pre-proj

// ---------------- helpers ----------------
__device__ __forceinline__ uint32_t f2tf32(float f) {
    uint32_t r;
    asm("cvt.rna.tf32.f32 %0, %1;" : "=r"(r) : "f"(f));
    return r;
}
__device__ __forceinline__ void cp16(void* smemp, const void* g) {
    uint32_t s = (uint32_t)__cvta_generic_to_shared(smemp);
    asm volatile("cp.async.cg.shared.global [%0], [%1], 16;" :: "r"(s), "l"(g));
}
__device__ __forceinline__ void cp_commit() { asm volatile("cp.async.commit_group;"); }
__device__ __forceinline__ void mma_tf32(float c[4], const uint32_t a[4], const uint32_t b[2]) {
    asm volatile(
        "mma.sync.aligned.m16n8k8.row.col.f32.tf32.tf32.f32 "
        "{%0,%1,%2,%3}, {%4,%5,%6,%7}, {%8,%9}, {%0,%1,%2,%3};"
        : "+f"(c[0]), "+f"(c[1]), "+f"(c[2]), "+f"(c[3])
        : "r"(a[0]), "r"(a[1]), "r"(a[2]), "r"(a[3]), "r"(b[0]), "r"(b[1]));
}

// ---------------- rel-pos bias gather ----------------
__global__ void bias_kernel(const float* __restrict__ table,
                            const int*   __restrict__ ridx) {
    int nm = blockIdx.x * blockDim.x + threadIdx.x;
    if (nm >= NTOK * NTOK) return;
    int ri = ridx[nm];
    #pragma unroll
    for (int h = 0; h < NH; h++)
        g_bias[h * NTOK * NTOK + nm] = table[ri * NH + h];
}

// ---------------- tf32 NT GEMM: C[m][n] = sum_k A[m][k]*B[n][k] + bias[n] -----
// BM=128, BN=128, BK=32, 256 threads (8 warps, 2x4), warp tile 64x32.
#define GSS 36      // smem row stride (floats), conflict-free fragment loads
__global__ __launch_bounds__(256)
void gemm_tf32(const float* __restrict__ A, const float* __restrict__ B,
               const float* __restrict__ bias, float* __restrict__ C,
               int M, int N, int K)
{
    extern __shared__ float sm[];
    float* As = sm;                    // 2 stages * 128*GSS
    float* Bs = sm + 2 * 128 * GSS;

    const int tid  = threadIdx.x;
    const int warp = tid >> 5, lane = tid & 31;
    const int qg   = lane >> 2, tg = lane & 3;
    const int wm   = (warp >> 2) * 64;     // 0 or 64
    const int wn   = (warp & 3) * 32;      // 0,32,64,96
    const int row0 = blockIdx.y * 128, col0 = blockIdx.x * 128;

    float c[4][4][4];
    #pragma unroll
    for (int i = 0; i < 4; i++)
        #pragma unroll
        for (int j = 0; j < 4; j++)
            #pragma unroll
            for (int t = 0; t < 4; t++) c[i][j][t] = 0.0f;

    const int KT = K / 32;

    // async tile loaders: 1024 float4 per matrix per stage, 4 per thread
    auto load_stage = [&](int stage, int k0) {
        #pragma unroll
        for (int i = 0; i < 4; i++) {
            int id = tid + i * 256;
            int r = id >> 3, c4 = (id & 7) * 4;
            cp16(As + stage * 128 * GSS + r * GSS + c4,
                 A + (size_t)(row0 + r) * K + k0 + c4);
            cp16(Bs + stage * 128 * GSS + r * GSS + c4,
                 B + (size_t)(col0 + r) * K + k0 + c4);
        }
        cp_commit();
    };

    load_stage(0, 0);

    for (int kt = 0; kt < KT; kt++) {
        int buf = kt & 1;
        if (kt + 1 < KT) load_stage(buf ^ 1, (kt + 1) * 32);
        if (kt + 1 < KT) { asm volatile("cp.async.wait_group 1;"); }
        else             { asm volatile("cp.async.wait_group 0;"); }
        __syncthreads();

        const float* Asb = As + buf * 128 * GSS;
        const float* Bsb = Bs + buf * 128 * GSS;

        #pragma unroll
        for (int ks = 0; ks < 4; ks++) {
            int kk = ks * 8;
            uint32_t af[4][4], bf[4][2];
            #pragma unroll
            for (int i = 0; i < 4; i++) {
                const float* p = Asb + (wm + i * 16 + qg) * GSS + kk + tg;
                af[i][0] = f2tf32(p[0]);
                af[i][1] = f2tf32(p[8 * GSS]);
                af[i][2] = f2tf32(p[4]);
                af[i][3] = f2tf32(p[8 * GSS + 4]);
            }
            #pragma unroll
            for (int j = 0; j < 4; j++) {
                const float* p = Bsb + (wn + j * 8 + qg) * GSS + kk + tg;
                bf[j][0] = f2tf32(p[0]);
                bf[j][1] = f2tf32(p[4]);
            }
            #pragma unroll
            for (int i = 0; i < 4; i++)
                #pragma unroll
                for (int j = 0; j < 4; j++)
                    mma_tf32(c[i][j], af[i], bf[j]);
        }
        __syncthreads();
    }

    // epilogue: add bias, float2 stores
    #pragma unroll
    for (int i = 0; i < 4; i++) {
        int row = row0 + wm + i * 16 + qg;
        #pragma unroll
        for (int j = 0; j < 4; j++) {
            int col = col0 + wn + j * 8 + 2 * tg;
            float b0 = bias[col], b1 = bias[col + 1];
            float2 lo = make_float2(c[i][j][0] + b0, c[i][j][1] + b1);
            float2 hi = make_float2(c[i][j][2] + b0, c[i][j][3] + b1);
            *(float2*)&C[(size_t)row * N + col]       = lo;
            *(float2*)&C[(size_t)(row + 8) * N + col] = hi;
        }
    }
}

// ---------------- attention: CTA per (b,h), warp per 32 rows, lane per 2 keys --
#define SKT 258                      // transposed K/V row stride
__global__ __launch_bounds__(256)
void attn2(const float* __restrict__ mask)
{
    extern __shared__ float smn[];
    float* q_s = smn;                         // 256*32
    float* kT  = smn + 8192;                  // 32*258 (kT[d][m])
    float* vT  = kT + 32 * SKT;               // 32*258
    float* red = vT + 32 * SKT;               // 8 * 32*33

    const int bh = blockIdx.x;
    const int b  = bh >> 3;
    const int h  = bh & 7;
    const int tid = threadIdx.x;
    const int warp = tid >> 5, lane = tid & 31;

    const float scale = 0.17677669529663687f;   // 32^-0.5
    const float* base = g_qkv + (size_t)b * NTOK * QKVD;

    // stage q (scaled), K^T, V^T  — coalesced global reads
    for (int i = tid; i < NTOK * HD; i += 256) {
        int m = i >> 5, d = i & 31;
        q_s[m * 32 + d]  = base[m * QKVD +       h * 32 + d] * scale;
        kT[d * SKT + m]  = base[m * QKVD + 256 + h * 32 + d];
        vT[d * SKT + m]  = base[m * QKVD + 512 + h * 32 + d];
    }
    __syncthreads();

    const float* bias_h = g_bias + (size_t)h * NTOK * NTOK;
    const float* mask_w = mask + (size_t)(b & 63) * NTOK * NTOK;
    float* redw = red + warp * (32 * 33);

    for (int r = 0; r < 32; r++) {
        const int n = warp * 32 + r;
        float q[HD];
        #pragma unroll
        for (int d = 0; d < HD; d++) q[d] = q_s[n * 32 + d];

        const float2* brow = (const float2*)(bias_h + (size_t)n * NTOK);
        const float2* mrow = (const float2*)(mask_w + (size_t)n * NTOK);

        float mrun = -1e30f, lrun = 0.0f;
        float acc[HD];
        #pragma unroll
        for (int d = 0; d < HD; d++) acc[d] = 0.0f;

        #pragma unroll
        for (int kb = 0; kb < 4; kb++) {
            float2 bb = brow[kb * 32 + lane];
            float2 mm = mrow[kb * 32 + lane];
            const int off = kb * 64 + lane * 2;

            // two keys per lane, split dependency chains
            float s0a = 0.f, s0b = 0.f, s1a = 0.f, s1b = 0.f;
            #pragma unroll
            for (int d = 0; d < HD; d += 2) {
                float2 k0 = *(const float2*)(kT + d * SKT + off);
                float2 k1 = *(const float2*)(kT + (d + 1) * SKT + off);
                s0a = fmaf(q[d],     k0.x, s0a); s1a = fmaf(q[d],     k0.y, s1a);
                s0b = fmaf(q[d + 1], k1.x, s0b); s1b = fmaf(q[d + 1], k1.y, s1b);
            }
            float s0 = s0a + s0b + bb.x + mm.x;
            float s1 = s1a + s1b + bb.y + mm.y;

            float bm = fmaxf(s0, s1);
            #pragma unroll
            for (int o = 16; o > 0; o >>= 1)
                bm = fmaxf(bm, __shfl_xor_sync(0xffffffffu, bm, o));

            if (bm > mrun) {                       // warp-uniform branch
                float cor = __expf(mrun - bm);
                lrun *= cor;
                #pragma unroll
                for (int d = 0; d < HD; d++) acc[d] *= cor;
                mrun = bm;
            }
            float p0 = __expf(s0 - mrun);
            float p1 = __expf(s1 - mrun);
            lrun += p0 + p1;

            #pragma unroll
            for (int d = 0; d < HD; d++) {
                float2 v2 = *(const float2*)(vT + d * SKT + off);
                acc[d] = fmaf(p0, v2.x, acc[d]);
                acc[d] = fmaf(p1, v2.y, acc[d]);
            }
        }

        #pragma unroll
        for (int o = 16; o > 0; o >>= 1)
            lrun += __shfl_xor_sync(0xffffffffu, lrun, o);
        float inv = 1.0f / lrun;

        // cross-lane reduction via padded smem transpose
        #pragma unroll
        for (int d = 0; d < HD; d++) redw[lane * 33 + d] = acc[d];
        __syncwarp();
        float sum = 0.0f;
        #pragma unroll
        for (int j = 0; j < 32; j++) sum += redw[j * 33 + lane];
        g_att[((size_t)b * NTOK + n) * CDIM + h * 32 + lane] = sum * inv;
        __syncwarp();
    }
}

// --------------------------------------------------------------------------
extern "C" void kernel_launch(void* const* d_in, const int* in_sizes, int n_in,
                              void* d_out, int out_size)
{
    const float* x      = (const float*)d_in[0];
    const float* mask   = (const float*)d_in[1];
    const float* qkv_w  = (const float*)d_in[2];
    const float* qkv_b  = (const float*)d_in[3];
    const float* proj_w = (const float*)d_in[4];
    const float* proj_b = (const float*)d_in[5];
    const float* table  = (const float*)d_in[6];
    const int*   ridx   = (const int*)d_in[7];
    float* out = (float*)d_out;

    float *qkv_ptr = nullptr, *att_ptr = nullptr;
    cudaGetSymbolAddress((void**)&qkv_ptr, g_qkv);
    cudaGetSymbolAddress((void**)&att_ptr, g_att);

    const int gemm_smem = 2 * 2 * 128 * GSS * 4;          // 73728 B
    const int attn_smem = (8192 + 2 * 32 * SKT + 8 * 32 * 33) * 4;  // 132608 B
    cudaFuncSetAttribute(gemm_tf32, cudaFuncAttributeMaxDynamicSharedMemorySize, gemm_smem);
    cudaFuncSetAttribute(attn2,     cudaFuncAttributeMaxDynamicSharedMemorySize, attn_smem);

    // 1) rel-pos bias gather (H,N,N)
    bias_kernel<<<(NTOK * NTOK + 255) / 256, 256>>>(table, ridx);

    // 2) QKV projection: (49152,256) x (768,256)^T -> (49152,768)
    gemm_tf32<<<dim3(QKVD / 128, (NBATCH * NTOK) / 128), 256, gemm_smem>>>(
        x, qkv_w, qkv_b, qkv_ptr, NBATCH * NTOK, QKVD, CDIM);

    // 3) window attention
    attn2<<<NBATCH * NH, 256, attn_smem>>>(mask);

    // 4) output projection: (49152,256) x (256,256)^T -> d_out
    gemm_tf32<<<dim3(CDIM / 128, (NBATCH * NTOK) / 128), 256, gemm_smem>>>(
        att_ptr, proj_w, proj_b, out, NBATCH * NTOK, CDIM, CDIM);
}

// round 3
// speedup vs baseline: 3.7744x; 2.6254x over previous
#include <cuda_runtime.h>
#include <math.h>
#include <stdint.h>

#define NBATCH 192
#define NTOK   256
#define CDIM   256
#define NH     8
#define HD     32
#define QKVD   768   // 3*C

// ---------------- scratch (static __device__, no runtime alloc) ----------------
__device__ float g_qkv [NBATCH * NTOK * QKVD];   // (B, N, 3*H*hd)
__device__ float g_bias[NH * NTOK * NTOK];       // (H, N, N)
__device__ float g_att [NBATCH * NTOK * CDIM];   // attention output pre-proj

// ---------------- helpers ----------------
__device__ __forceinline__ uint32_t f2tf32(float f) {
    uint32_t r;
    asm("cvt.rna.tf32.f32 %0, %1;" : "=r"(r) : "f"(f));
    return r;
}
__device__ __forceinline__ void cp16(void* smemp, const void* g) {
    uint32_t s = (uint32_t)__cvta_generic_to_shared(smemp);
    asm volatile("cp.async.cg.shared.global [%0], [%1], 16;" :: "r"(s), "l"(g));
}
__device__ __forceinline__ void cp_commit() { asm volatile("cp.async.commit_group;"); }
__device__ __forceinline__ void mma_tf32(float c[4], const uint32_t a[4], const uint32_t b[2]) {
    asm volatile(
        "mma.sync.aligned.m16n8k8.row.col.f32.tf32.tf32.f32 "
        "{%0,%1,%2,%3}, {%4,%5,%6,%7}, {%8,%9}, {%0,%1,%2,%3};"
        : "+f"(c[0]), "+f"(c[1]), "+f"(c[2]), "+f"(c[3])
        : "r"(a[0]), "r"(a[1]), "r"(a[2]), "r"(a[3]), "r"(b[0]), "r"(b[1]));
}

// ---------------- rel-pos bias gather ----------------
__global__ void bias_kernel(const float* __restrict__ table,
                            const int*   __restrict__ ridx) {
    int nm = blockIdx.x * blockDim.x + threadIdx.x;
    if (nm >= NTOK * NTOK) return;
    int ri = ridx[nm];
    #pragma unroll
    for (int h = 0; h < NH; h++)
        g_bias[h * NTOK * NTOK + nm] = table[ri * NH + h];
}

// ---------------- tf32 NT GEMM (3-stage cp.async): C = A*B^T + bias ----------
#define GSS 36
#define GST (128 * GSS)
__global__ __launch_bounds__(256)
void gemm_tf32(const float* __restrict__ A, const float* __restrict__ B,
               const float* __restrict__ bias, float* __restrict__ C,
               int M, int N, int K)
{
    extern __shared__ float sm[];
    float* As = sm;               // 3 stages * 128*GSS
    float* Bs = sm + 3 * GST;

    const int tid  = threadIdx.x;
    const int warp = tid >> 5, lane = tid & 31;
    const int qg   = lane >> 2, tg = lane & 3;
    const int wm   = (warp >> 2) * 64;
    const int wn   = (warp & 3) * 32;
    const int row0 = blockIdx.y * 128, col0 = blockIdx.x * 128;

    float c[4][4][4];
    #pragma unroll
    for (int i = 0; i < 4; i++)
        #pragma unroll
        for (int j = 0; j < 4; j++)
            #pragma unroll
            for (int t = 0; t < 4; t++) c[i][j][t] = 0.0f;

    const int KT = K / 32;

    auto load_stage = [&](int stage, int k0) {
        #pragma unroll
        for (int i = 0; i < 4; i++) {
            int id = tid + i * 256;
            int r = id >> 3, c4 = (id & 7) * 4;
            cp16(As + stage * GST + r * GSS + c4,
                 A + (size_t)(row0 + r) * K + k0 + c4);
            cp16(Bs + stage * GST + r * GSS + c4,
                 B + (size_t)(col0 + r) * K + k0 + c4);
        }
        cp_commit();
    };

    load_stage(0, 0);
    load_stage(1, 32);

    for (int kt = 0; kt < KT; kt++) {
        if (kt < KT - 1) { asm volatile("cp.async.wait_group 1;"); }
        else             { asm volatile("cp.async.wait_group 0;"); }
        __syncthreads();
        if (kt + 2 < KT) load_stage((kt + 2) % 3, (kt + 2) * 32);

        const float* Asb = As + (kt % 3) * GST;
        const float* Bsb = Bs + (kt % 3) * GST;

        #pragma unroll
        for (int ks = 0; ks < 4; ks++) {
            int kk = ks * 8;
            uint32_t af[4][4], bf[4][2];
            #pragma unroll
            for (int i = 0; i < 4; i++) {
                const float* p = Asb + (wm + i * 16 + qg) * GSS + kk + tg;
                af[i][0] = f2tf32(p[0]);
                af[i][1] = f2tf32(p[8 * GSS]);
                af[i][2] = f2tf32(p[4]);
                af[i][3] = f2tf32(p[8 * GSS + 4]);
            }
            #pragma unroll
            for (int j = 0; j < 4; j++) {
                const float* p = Bsb + (wn + j * 8 + qg) * GSS + kk + tg;
                bf[j][0] = f2tf32(p[0]);
                bf[j][1] = f2tf32(p[4]);
            }
            #pragma unroll
            for (int i = 0; i < 4; i++)
                #pragma unroll
                for (int j = 0; j < 4; j++)
                    mma_tf32(c[i][j], af[i], bf[j]);
        }
        __syncthreads();
    }

    #pragma unroll
    for (int i = 0; i < 4; i++) {
        int row = row0 + wm + i * 16 + qg;
        #pragma unroll
        for (int j = 0; j < 4; j++) {
            int col = col0 + wn + j * 8 + 2 * tg;
            float b0 = bias[col], b1 = bias[col + 1];
            float2 lo = make_float2(c[i][j][0] + b0, c[i][j][1] + b1);
            float2 hi = make_float2(c[i][j][2] + b0, c[i][j][3] + b1);
            *(float2*)&C[(size_t)row * N + col]       = lo;
            *(float2*)&C[(size_t)(row + 8) * N + col] = hi;
        }
    }
}

// ---------------- tensor-core flash attention: CTA per (b,h) ------------------
// 8 warps x 32 query rows. S = Q K^T (tf32 mma), online softmax, P V (tf32 mma).
#define QS 36   // Q smem stride: A-frag loads bank = 4*qg+tg = lane  (CF)
#define KS 36   // K smem stride: B-frag loads bank = 4*qg+tg        (CF)
#define VS 40   // V smem stride: B-frag loads bank = 8*tg+qg        (CF)
#define PS 68   // P smem stride: A-frag loads bank = 4*qg+tg        (CF)
__global__ __launch_bounds__(256, 1)
void attn_mma(const float* __restrict__ mask)
{
    extern __shared__ float sm[];
    float* Qs = sm;                  // 256*36
    float* Ks = Qs + 256 * QS;       // 256*36
    float* Vs = Ks + 256 * KS;       // 256*40
    float* Ps = Vs + 256 * VS;       // 8 * 32*68

    const int bh = blockIdx.x, b = bh >> 3, h = bh & 7;
    const int tid = threadIdx.x, warp = tid >> 5, lane = tid & 31;
    const int qg = lane >> 2, tg = lane & 3;
    const float scale = 0.17677669529663687f;   // 32^-0.5

    const float* base = g_qkv + (size_t)b * NTOK * QKVD;
    for (int i = tid; i < NTOK * HD; i += 256) {
        int m = i >> 5, d = i & 31;
        Qs[m * QS + d] = base[m * QKVD +       h * 32 + d] * scale;
        Ks[m * KS + d] = base[m * QKVD + 256 + h * 32 + d];
        Vs[m * VS + d] = base[m * QKVD + 512 + h * 32 + d];
    }
    __syncthreads();

    const int wm = warp * 32;
    float* Pw = Ps + warp * 32 * PS;
    const float* bias_h = g_bias + (size_t)h * NTOK * NTOK;
    const float* mask_w = mask + (size_t)(b & 63) * NTOK * NTOK;

    // persistent Q fragments (tf32)
    uint32_t qf[2][4][4];
    #pragma unroll
    for (int i = 0; i < 2; i++)
        #pragma unroll
        for (int kt = 0; kt < 4; kt++) {
            const float* p = Qs + (wm + 16 * i + qg) * QS + 8 * kt + tg;
            qf[i][kt][0] = f2tf32(p[0]);
            qf[i][kt][1] = f2tf32(p[8 * QS]);
            qf[i][kt][2] = f2tf32(p[4]);
            qf[i][kt][3] = f2tf32(p[8 * QS + 4]);
        }

    float O[2][4][4];
    #pragma unroll
    for (int i = 0; i < 2; i++)
        #pragma unroll
        for (int j = 0; j < 4; j++)
            #pragma unroll
            for (int t = 0; t < 4; t++) O[i][j][t] = 0.0f;
    float mrun[4] = {-1e30f, -1e30f, -1e30f, -1e30f};
    float lrun[4] = {0.f, 0.f, 0.f, 0.f};

    for (int nb = 0; nb < 4; nb++) {
        const int n0 = nb * 64;

        // ---- S = Q K^T over this 64-key block
        float S[2][8][4];
        #pragma unroll
        for (int i = 0; i < 2; i++)
            #pragma unroll
            for (int j = 0; j < 8; j++)
                #pragma unroll
                for (int t = 0; t < 4; t++) S[i][j][t] = 0.0f;

        #pragma unroll
        for (int kt = 0; kt < 4; kt++) {
            #pragma unroll
            for (int j = 0; j < 8; j++) {
                uint32_t bf[2];
                const float* p = Ks + (n0 + 8 * j + qg) * KS + 8 * kt + tg;
                bf[0] = f2tf32(p[0]);
                bf[1] = f2tf32(p[4]);
                mma_tf32(S[0][j], qf[0][kt], bf);
                mma_tf32(S[1][j], qf[1][kt], bf);
            }
        }

        // ---- add bias + shift mask
        #pragma unroll
        for (int i = 0; i < 2; i++) {
            int row = wm + 16 * i + qg;
            #pragma unroll
            for (int j = 0; j < 8; j++) {
                int col = n0 + 8 * j + 2 * tg;
                float2 b0 = *(const float2*)(bias_h + (size_t)row * NTOK + col);
                float2 m0 = *(const float2*)(mask_w + (size_t)row * NTOK + col);
                S[i][j][0] += b0.x + m0.x;
                S[i][j][1] += b0.y + m0.y;
                float2 b1 = *(const float2*)(bias_h + (size_t)(row + 8) * NTOK + col);
                float2 m1 = *(const float2*)(mask_w + (size_t)(row + 8) * NTOK + col);
                S[i][j][2] += b1.x + m1.x;
                S[i][j][3] += b1.y + m1.y;
            }
        }

        // ---- online softmax (4 rows per thread), write P to per-warp smem
        #pragma unroll
        for (int i = 0; i < 2; i++)
            #pragma unroll
            for (int e = 0; e < 2; e++) {
                const int r = 2 * i + e;
                float mx = -1e30f;
                #pragma unroll
                for (int j = 0; j < 8; j++)
                    mx = fmaxf(mx, fmaxf(S[i][j][2 * e], S[i][j][2 * e + 1]));
                mx = fmaxf(mx, __shfl_xor_sync(0xffffffffu, mx, 1));
                mx = fmaxf(mx, __shfl_xor_sync(0xffffffffu, mx, 2));

                float mnew = fmaxf(mrun[r], mx);
                float cor = __expf(mrun[r] - mnew);
                lrun[r] *= cor;
                #pragma unroll
                for (int j = 0; j < 4; j++) {
                    O[i][j][2 * e]     *= cor;
                    O[i][j][2 * e + 1] *= cor;
                }
                mrun[r] = mnew;

                float psum = 0.0f;
                float* prow = Pw + (16 * i + qg + 8 * e) * PS + 2 * tg;
                #pragma unroll
                for (int j = 0; j < 8; j++) {
                    float p0 = __expf(S[i][j][2 * e]     - mnew);
                    float p1 = __expf(S[i][j][2 * e + 1] - mnew);
                    psum += p0 + p1;
                    *(float2*)(prow + 8 * j) = make_float2(p0, p1);
                }
                psum += __shfl_xor_sync(0xffffffffu, psum, 1);
                psum += __shfl_xor_sync(0xffffffffu, psum, 2);
                lrun[r] += psum;
            }
        __syncwarp();

        // ---- O += P V  (k = 64 keys, 8 k-tiles)
        #pragma unroll
        for (int ks = 0; ks < 8; ks++) {
            uint32_t af[2][4];
            #pragma unroll
            for (int i = 0; i < 2; i++) {
                const float* p = Pw + (16 * i + qg) * PS + 8 * ks + tg;
                af[i][0] = f2tf32(p[0]);
                af[i][1] = f2tf32(p[8 * PS]);
                af[i][2] = f2tf32(p[4]);
                af[i][3] = f2tf32(p[8 * PS + 4]);
            }
            #pragma unroll
            for (int j = 0; j < 4; j++) {
                uint32_t bf[2];
                const float* p = Vs + (n0 + 8 * ks + tg) * VS + 8 * j + qg;
                bf[0] = f2tf32(p[0]);
                bf[1] = f2tf32(p[4 * VS]);
                mma_tf32(O[0][j], af[0], bf);
                mma_tf32(O[1][j], af[1], bf);
            }
        }
        __syncwarp();
    }

    // ---- epilogue: normalize and write (B,N,C) with head offset
    float inv[4];
    #pragma unroll
    for (int r = 0; r < 4; r++) inv[r] = 1.0f / lrun[r];

    #pragma unroll
    for (int i = 0; i < 2; i++) {
        int row = wm + 16 * i + qg;
        #pragma unroll
        for (int j = 0; j < 4; j++) {
            int col = h * 32 + 8 * j + 2 * tg;
            *(float2*)&g_att[((size_t)b * NTOK + row) * CDIM + col] =
                make_float2(O[i][j][0] * inv[2 * i], O[i][j][1] * inv[2 * i]);
            *(float2*)&g_att[((size_t)b * NTOK + row + 8) * CDIM + col] =
                make_float2(O[i][j][2] * inv[2 * i + 1], O[i][j][3] * inv[2 * i + 1]);
        }
    }
}

// --------------------------------------------------------------------------
extern "C" void kernel_launch(void* const* d_in, const int* in_sizes, int n_in,
                              void* d_out, int out_size)
{
    const float* x      = (const float*)d_in[0];
    const float* mask   = (const float*)d_in[1];
    const float* qkv_w  = (const float*)d_in[2];
    const float* qkv_b  = (const float*)d_in[3];
    const float* proj_w = (const float*)d_in[4];
    const float* proj_b = (const float*)d_in[5];
    const float* table  = (const float*)d_in[6];
    const int*   ridx   = (const int*)d_in[7];
    float* out = (float*)d_out;

    float *qkv_ptr = nullptr, *att_ptr = nullptr;
    cudaGetSymbolAddress((void**)&qkv_ptr, g_qkv);
    cudaGetSymbolAddress((void**)&att_ptr, g_att);

    const int gemm_smem = 3 * 2 * GST * 4;                                   // 110592 B
    const int attn_smem = (256 * QS + 256 * KS + 256 * VS + 8 * 32 * PS) * 4; // 184320 B
    cudaFuncSetAttribute(gemm_tf32, cudaFuncAttributeMaxDynamicSharedMemorySize, gemm_smem);
    cudaFuncSetAttribute(attn_mma,  cudaFuncAttributeMaxDynamicSharedMemorySize, attn_smem);

    // 1) rel-pos bias gather (H,N,N)
    bias_kernel<<<(NTOK * NTOK + 255) / 256, 256>>>(table, ridx);

    // 2) QKV projection: (49152,256) x (768,256)^T -> (49152,768)
    gemm_tf32<<<dim3(QKVD / 128, (NBATCH * NTOK) / 128), 256, gemm_smem>>>(
        x, qkv_w, qkv_b, qkv_ptr, NBATCH * NTOK, QKVD, CDIM);

    // 3) window attention (tensor-core flash)
    attn_mma<<<NBATCH * NH, 256, attn_smem>>>(mask);

    // 4) output projection: (49152,256) x (256,256)^T -> d_out
    gemm_tf32<<<dim3(CDIM / 128, (NBATCH * NTOK) / 128), 256, gemm_smem>>>(
        att_ptr, proj_w, proj_b, out, NBATCH * NTOK, CDIM, CDIM);
}

// round 4
// speedup vs baseline: 3.9996x; 1.0597x over previous
#include <cuda_runtime.h>
#include <math.h>
#include <stdint.h>

#define NBATCH 192
#define NTOK   256
#define CDIM   256
#define NH     8
#define HD     32
#define QKVD   768   // 3*C

// ---------------- scratch (static __device__, no runtime alloc) ----------------
__device__ float g_qkv [NBATCH * NTOK * QKVD];   // (B, N, 3*H*hd), tf32-rounded, Q pre-scaled
__device__ float g_bias[NH * NTOK * NTOK];       // (H, N, N)
__device__ float g_att [NBATCH * NTOK * CDIM];   // attention out, tf32-rounded
__device__ float g_xr  [NBATCH * NTOK * CDIM];   // x, tf32-rounded
__device__ float g_wr  [QKVD * CDIM + CDIM * CDIM]; // rounded qkv_w | proj_w

// ---------------- helpers ----------------
__device__ __forceinline__ uint32_t f2tf32(float f) {
    uint32_t r;
    asm("cvt.rna.tf32.f32 %0, %1;" : "=r"(r) : "f"(f));
    return r;
}
__device__ __forceinline__ float tf32r(float f) { return __uint_as_float(f2tf32(f)); }
__device__ __forceinline__ void cp16(void* smemp, const void* g) {
    uint32_t s = (uint32_t)__cvta_generic_to_shared(smemp);
    asm volatile("cp.async.cg.shared.global [%0], [%1], 16;" :: "r"(s), "l"(g));
}
__device__ __forceinline__ void cp_commit() { asm volatile("cp.async.commit_group;"); }
__device__ __forceinline__ void mma_tf32(float c[4], const uint32_t a[4], const uint32_t b[2]) {
    asm volatile(
        "mma.sync.aligned.m16n8k8.row.col.f32.tf32.tf32.f32 "
        "{%0,%1,%2,%3}, {%4,%5,%6,%7}, {%8,%9}, {%0,%1,%2,%3};"
        : "+f"(c[0]), "+f"(c[1]), "+f"(c[2]), "+f"(c[3])
        : "r"(a[0]), "r"(a[1]), "r"(a[2]), "r"(a[3]), "r"(b[0]), "r"(b[1]));
}
__device__ __forceinline__ uint32_t lduf(const float* p) {
    return *(const uint32_t*)p;     // operand already tf32-rounded in memory
}

// ---------------- prep: round a buffer to tf32 (RNA) ----------------
__global__ void round_kernel(const float4* __restrict__ in, float4* __restrict__ out, int n4) {
    int i = blockIdx.x * blockDim.x + threadIdx.x;
    if (i >= n4) return;
    float4 v = in[i];
    v.x = tf32r(v.x); v.y = tf32r(v.y); v.z = tf32r(v.z); v.w = tf32r(v.w);
    out[i] = v;
}

// ---------------- rel-pos bias gather ----------------
__global__ void bias_kernel(const float* __restrict__ table,
                            const int*   __restrict__ ridx) {
    int nm = blockIdx.x * blockDim.x + threadIdx.x;
    if (nm >= NTOK * NTOK) return;
    int ri = ridx[nm];
    #pragma unroll
    for (int h = 0; h < NH; h++)
        g_bias[h * NTOK * NTOK + nm] = table[ri * NH + h];
}

// ---------------- tf32 NT GEMM (3-stage cp.async): C = A*B^T + bias ----------
// QKV_MODE: pre-scale Q columns (col<256) and round output to tf32.
#define GSS 36
#define GST (128 * GSS)
template<bool QKV_MODE>
__global__ __launch_bounds__(256)
void gemm_tf32(const float* __restrict__ A, const float* __restrict__ B,
               const float* __restrict__ bias, float* __restrict__ C,
               int M, int N, int K)
{
    extern __shared__ float sm[];
    float* As = sm;
    float* Bs = sm + 3 * GST;

    const int tid  = threadIdx.x;
    const int warp = tid >> 5, lane = tid & 31;
    const int qg   = lane >> 2, tg = lane & 3;
    const int wm   = (warp >> 2) * 64;
    const int wn   = (warp & 3) * 32;
    const int row0 = blockIdx.y * 128, col0 = blockIdx.x * 128;

    float c[4][4][4];
    #pragma unroll
    for (int i = 0; i < 4; i++)
        #pragma unroll
        for (int j = 0; j < 4; j++)
            #pragma unroll
            for (int t = 0; t < 4; t++) c[i][j][t] = 0.0f;

    const int KT = K / 32;

    auto load_stage = [&](int stage, int k0) {
        #pragma unroll
        for (int i = 0; i < 4; i++) {
            int id = tid + i * 256;
            int r = id >> 3, c4 = (id & 7) * 4;
            cp16(As + stage * GST + r * GSS + c4,
                 A + (size_t)(row0 + r) * K + k0 + c4);
            cp16(Bs + stage * GST + r * GSS + c4,
                 B + (size_t)(col0 + r) * K + k0 + c4);
        }
        cp_commit();
    };

    load_stage(0, 0);
    load_stage(1, 32);

    for (int kt = 0; kt < KT; kt++) {
        if (kt < KT - 1) { asm volatile("cp.async.wait_group 1;"); }
        else             { asm volatile("cp.async.wait_group 0;"); }
        __syncthreads();
        if (kt + 2 < KT) load_stage((kt + 2) % 3, (kt + 2) * 32);

        const float* Asb = As + (kt % 3) * GST;
        const float* Bsb = Bs + (kt % 3) * GST;

        #pragma unroll
        for (int ks = 0; ks < 4; ks++) {
            int kk = ks * 8;
            uint32_t af[4][4], bf[4][2];
            #pragma unroll
            for (int i = 0; i < 4; i++) {
                const float* p = Asb + (wm + i * 16 + qg) * GSS + kk + tg;
                af[i][0] = lduf(p);
                af[i][1] = lduf(p + 8 * GSS);
                af[i][2] = lduf(p + 4);
                af[i][3] = lduf(p + 8 * GSS + 4);
            }
            #pragma unroll
            for (int j = 0; j < 4; j++) {
                const float* p = Bsb + (wn + j * 8 + qg) * GSS + kk + tg;
                bf[j][0] = lduf(p);
                bf[j][1] = lduf(p + 4);
            }
            #pragma unroll
            for (int i = 0; i < 4; i++)
                #pragma unroll
                for (int j = 0; j < 4; j++)
                    mma_tf32(c[i][j], af[i], bf[j]);
        }
        __syncthreads();
    }

    const float scale = 0.17677669529663687f;   // 32^-0.5
    #pragma unroll
    for (int i = 0; i < 4; i++) {
        int row = row0 + wm + i * 16 + qg;
        #pragma unroll
        for (int j = 0; j < 4; j++) {
            int col = col0 + wn + j * 8 + 2 * tg;
            float b0 = bias[col], b1 = bias[col + 1];
            float v00 = c[i][j][0] + b0, v01 = c[i][j][1] + b1;
            float v10 = c[i][j][2] + b0, v11 = c[i][j][3] + b1;
            if (QKV_MODE) {
                if (col < 256) { v00 *= scale; v01 *= scale; v10 *= scale; v11 *= scale; }
                v00 = tf32r(v00); v01 = tf32r(v01); v10 = tf32r(v10); v11 = tf32r(v11);
            }
            *(float2*)&C[(size_t)row * N + col]       = make_float2(v00, v01);
            *(float2*)&C[(size_t)(row + 8) * N + col] = make_float2(v10, v11);
        }
    }
}

// ---------------- tensor-core flash attention: CTA per (b,h) ------------------
#define QS 36
#define KS 36
#define VS 40
#define PS 68
__global__ __launch_bounds__(256, 1)
void attn_mma(const float* __restrict__ mask)
{
    extern __shared__ float sm[];
    float* Qs = sm;                  // 256*36
    float* Ks = Qs + 256 * QS;       // 256*36
    float* Vs = Ks + 256 * KS;       // 256*40
    float* Ps = Vs + 256 * VS;       // 8 * 32*68

    const int bh = blockIdx.x, b = bh >> 3, h = bh & 7;
    const int tid = threadIdx.x, warp = tid >> 5, lane = tid & 31;
    const int qg = lane >> 2, tg = lane & 3;

    // stage Q (already scaled+rounded), K, V via cp.async float4
    const float* base = g_qkv + (size_t)b * NTOK * QKVD + h * 32;
    #pragma unroll
    for (int id = tid; id < 2048; id += 256) {
        int m = id >> 3, c4 = (id & 7) * 4;
        const float* src = base + m * QKVD + c4;
        cp16(Qs + m * QS + c4, src);
        cp16(Ks + m * KS + c4, src + 256);
        cp16(Vs + m * VS + c4, src + 512);
    }
    cp_commit();
    asm volatile("cp.async.wait_group 0;");
    __syncthreads();

    const int wm = warp * 32;
    float* Pw = Ps + warp * 32 * PS;
    const float* bias_h = g_bias + (size_t)h * NTOK * NTOK;
    const float* mask_w = mask + (size_t)(b & 63) * NTOK * NTOK;

    // persistent Q fragments
    uint32_t qf[2][4][4];
    #pragma unroll
    for (int i = 0; i < 2; i++)
        #pragma unroll
        for (int kt = 0; kt < 4; kt++) {
            const float* p = Qs + (wm + 16 * i + qg) * QS + 8 * kt + tg;
            qf[i][kt][0] = lduf(p);
            qf[i][kt][1] = lduf(p + 8 * QS);
            qf[i][kt][2] = lduf(p + 4);
            qf[i][kt][3] = lduf(p + 8 * QS + 4);
        }

    float O[2][4][4];
    #pragma unroll
    for (int i = 0; i < 2; i++)
        #pragma unroll
        for (int j = 0; j < 4; j++)
            #pragma unroll
            for (int t = 0; t < 4; t++) O[i][j][t] = 0.0f;
    float mrun[4] = {-1e30f, -1e30f, -1e30f, -1e30f};
    float lrun[4] = {0.f, 0.f, 0.f, 0.f};

    for (int nb = 0; nb < 4; nb++) {
        const int n0 = nb * 64;

        // ---- init S with bias + mask (loads issue before the mma stream)
        float S[2][8][4];
        #pragma unroll
        for (int i = 0; i < 2; i++) {
            int row = wm + 16 * i + qg;
            #pragma unroll
            for (int j = 0; j < 8; j++) {
                int col = n0 + 8 * j + 2 * tg;
                float2 b0 = *(const float2*)(bias_h + (size_t)row * NTOK + col);
                float2 m0 = *(const float2*)(mask_w + (size_t)row * NTOK + col);
                float2 b1 = *(const float2*)(bias_h + (size_t)(row + 8) * NTOK + col);
                float2 m1 = *(const float2*)(mask_w + (size_t)(row + 8) * NTOK + col);
                S[i][j][0] = b0.x + m0.x;
                S[i][j][1] = b0.y + m0.y;
                S[i][j][2] = b1.x + m1.x;
                S[i][j][3] = b1.y + m1.y;
            }
        }

        // ---- S += Q K^T
        #pragma unroll
        for (int kt = 0; kt < 4; kt++) {
            #pragma unroll
            for (int j = 0; j < 8; j++) {
                uint32_t bf[2];
                const float* p = Ks + (n0 + 8 * j + qg) * KS + 8 * kt + tg;
                bf[0] = lduf(p);
                bf[1] = lduf(p + 4);
                mma_tf32(S[0][j], qf[0][kt], bf);
                mma_tf32(S[1][j], qf[1][kt], bf);
            }
        }

        // ---- online softmax (4 rows per thread), write rounded P to smem
        #pragma unroll
        for (int i = 0; i < 2; i++)
            #pragma unroll
            for (int e = 0; e < 2; e++) {
                const int r = 2 * i + e;
                float mx = -1e30f;
                #pragma unroll
                for (int j = 0; j < 8; j++)
                    mx = fmaxf(mx, fmaxf(S[i][j][2 * e], S[i][j][2 * e + 1]));
                mx = fmaxf(mx, __shfl_xor_sync(0xffffffffu, mx, 1));
                mx = fmaxf(mx, __shfl_xor_sync(0xffffffffu, mx, 2));

                float mnew = fmaxf(mrun[r], mx);
                float cor = __expf(mrun[r] - mnew);
                lrun[r] *= cor;
                #pragma unroll
                for (int j = 0; j < 4; j++) {
                    O[i][j][2 * e]     *= cor;
                    O[i][j][2 * e + 1] *= cor;
                }
                mrun[r] = mnew;

                float psum = 0.0f;
                float* prow = Pw + (16 * i + qg + 8 * e) * PS + 2 * tg;
                #pragma unroll
                for (int j = 0; j < 8; j++) {
                    float p0 = __expf(S[i][j][2 * e]     - mnew);
                    float p1 = __expf(S[i][j][2 * e + 1] - mnew);
                    psum += p0 + p1;
                    *(float2*)(prow + 8 * j) = make_float2(tf32r(p0), tf32r(p1));
                }
                psum += __shfl_xor_sync(0xffffffffu, psum, 1);
                psum += __shfl_xor_sync(0xffffffffu, psum, 2);
                lrun[r] += psum;
            }
        __syncwarp();

        // ---- O += P V
        #pragma unroll
        for (int ks = 0; ks < 8; ks++) {
            uint32_t af[2][4];
            #pragma unroll
            for (int i = 0; i < 2; i++) {
                const float* p = Pw + (16 * i + qg) * PS + 8 * ks + tg;
                af[i][0] = lduf(p);
                af[i][1] = lduf(p + 8 * PS);
                af[i][2] = lduf(p + 4);
                af[i][3] = lduf(p + 8 * PS + 4);
            }
            #pragma unroll
            for (int j = 0; j < 4; j++) {
                uint32_t bf[2];
                const float* p = Vs + (n0 + 8 * ks + tg) * VS + 8 * j + qg;
                bf[0] = lduf(p);
                bf[1] = lduf(p + 4 * VS);
                mma_tf32(O[0][j], af[0], bf);
                mma_tf32(O[1][j], af[1], bf);
            }
        }
        __syncwarp();
    }

    float inv[4];
    #pragma unroll
    for (int r = 0; r < 4; r++) inv[r] = 1.0f / lrun[r];

    #pragma unroll
    for (int i = 0; i < 2; i++) {
        int row = wm + 16 * i + qg;
        #pragma unroll
        for (int j = 0; j < 4; j++) {
            int col = h * 32 + 8 * j + 2 * tg;
            *(float2*)&g_att[((size_t)b * NTOK + row) * CDIM + col] =
                make_float2(tf32r(O[i][j][0] * inv[2 * i]), tf32r(O[i][j][1] * inv[2 * i]));
            *(float2*)&g_att[((size_t)b * NTOK + row + 8) * CDIM + col] =
                make_float2(tf32r(O[i][j][2] * inv[2 * i + 1]), tf32r(O[i][j][3] * inv[2 * i + 1]));
        }
    }
}

// --------------------------------------------------------------------------
extern "C" void kernel_launch(void* const* d_in, const int* in_sizes, int n_in,
                              void* d_out, int out_size)
{
    const float* x      = (const float*)d_in[0];
    const float* mask   = (const float*)d_in[1];
    const float* qkv_w  = (const float*)d_in[2];
    const float* qkv_b  = (const float*)d_in[3];
    const float* proj_w = (const float*)d_in[4];
    const float* proj_b = (const float*)d_in[5];
    const float* table  = (const float*)d_in[6];
    const int*   ridx   = (const int*)d_in[7];
    float* out = (float*)d_out;

    float *qkv_ptr, *att_ptr, *xr_ptr, *wr_ptr;
    cudaGetSymbolAddress((void**)&qkv_ptr, g_qkv);
    cudaGetSymbolAddress((void**)&att_ptr, g_att);
    cudaGetSymbolAddress((void**)&xr_ptr,  g_xr);
    cudaGetSymbolAddress((void**)&wr_ptr,  g_wr);
    float* qkvw_r = wr_ptr;
    float* projw_r = wr_ptr + QKVD * CDIM;

    const int gemm_smem = 3 * 2 * GST * 4;                                    // 110592 B
    const int attn_smem = (256 * QS + 256 * KS + 256 * VS + 8 * 32 * PS) * 4; // 184320 B
    cudaFuncSetAttribute(gemm_tf32<true>,  cudaFuncAttributeMaxDynamicSharedMemorySize, gemm_smem);
    cudaFuncSetAttribute(gemm_tf32<false>, cudaFuncAttributeMaxDynamicSharedMemorySize, gemm_smem);
    cudaFuncSetAttribute(attn_mma, cudaFuncAttributeMaxDynamicSharedMemorySize, attn_smem);

    // 0) prep: round x and weights to tf32 (RNA)
    {
        int n4 = NBATCH * NTOK * CDIM / 4;
        round_kernel<<<(n4 + 255) / 256, 256>>>((const float4*)x, (float4*)xr_ptr, n4);
        int w4 = QKVD * CDIM / 4;
        round_kernel<<<(w4 + 255) / 256, 256>>>((const float4*)qkv_w, (float4*)qkvw_r, w4);
        int p4 = CDIM * CDIM / 4;
        round_kernel<<<(p4 + 255) / 256, 256>>>((const float4*)proj_w, (float4*)projw_r, p4);
    }

    // 1) rel-pos bias gather
    bias_kernel<<<(NTOK * NTOK + 255) / 256, 256>>>(table, ridx);

    // 2) QKV projection (rounded output, Q pre-scaled)
    gemm_tf32<true><<<dim3(QKVD / 128, (NBATCH * NTOK) / 128), 256, gemm_smem>>>(
        xr_ptr, qkvw_r, qkv_b, qkv_ptr, NBATCH * NTOK, QKVD, CDIM);

    // 3) window attention (tensor-core flash)
    attn_mma<<<NBATCH * NH, 256, attn_smem>>>(mask);

    // 4) output projection
    gemm_tf32<false><<<dim3(CDIM / 128, (NBATCH * NTOK) / 128), 256, gemm_smem>>>(
        att_ptr, projw_r, proj_b, out, NBATCH * NTOK, CDIM, CDIM);
}

// round 5
// speedup vs baseline: 4.4819x; 1.1206x over previous
#include <cuda_runtime.h>
#include <math.h>
#include <stdint.h>

#define NBATCH 192
#define NTOK   256
#define CDIM   256
#define NH     8
#define HD     32
#define QKVD   768   // 3*C

// ---------------- scratch (static __device__, no runtime alloc) ----------------
__device__ float g_qkv [NBATCH * NTOK * QKVD];   // (B, N, 3*H*hd), tf32-rounded, Q pre-scaled
__device__ float g_bias[NH * NTOK * NTOK];       // (H, N, N)
__device__ float g_att [NBATCH * NTOK * CDIM];   // attention out, tf32-rounded
__device__ float g_wr  [QKVD * CDIM + CDIM * CDIM]; // rounded qkv_w | proj_w

// ---------------- helpers ----------------
__device__ __forceinline__ uint32_t f2tf32(float f) {
    uint32_t r;
    asm("cvt.rna.tf32.f32 %0, %1;" : "=r"(r) : "f"(f));
    return r;
}
__device__ __forceinline__ float tf32r(float f) { return __uint_as_float(f2tf32(f)); }
__device__ __forceinline__ void cp16(void* smemp, const void* g) {
    uint32_t s = (uint32_t)__cvta_generic_to_shared(smemp);
    asm volatile("cp.async.cg.shared.global [%0], [%1], 16;" :: "r"(s), "l"(g));
}
__device__ __forceinline__ void cp_commit() { asm volatile("cp.async.commit_group;"); }
__device__ __forceinline__ void mma_tf32(float c[4], const uint32_t a[4], const uint32_t b[2]) {
    asm volatile(
        "mma.sync.aligned.m16n8k8.row.col.f32.tf32.tf32.f32 "
        "{%0,%1,%2,%3}, {%4,%5,%6,%7}, {%8,%9}, {%0,%1,%2,%3};"
        : "+f"(c[0]), "+f"(c[1]), "+f"(c[2]), "+f"(c[3])
        : "r"(a[0]), "r"(a[1]), "r"(a[2]), "r"(a[3]), "r"(b[0]), "r"(b[1]));
}
__device__ __forceinline__ uint32_t lduf(const float* p) {
    return *(const uint32_t*)p;     // operand already tf32-rounded in memory
}

// ---------------- prep: round a buffer to tf32 (RNA) ----------------
__global__ void round_kernel(const float4* __restrict__ in, float4* __restrict__ out, int n4) {
    int i = blockIdx.x * blockDim.x + threadIdx.x;
    if (i >= n4) return;
    float4 v = in[i];
    v.x = tf32r(v.x); v.y = tf32r(v.y); v.z = tf32r(v.z); v.w = tf32r(v.w);
    out[i] = v;
}

// ---------------- rel-pos bias gather ----------------
__global__ void bias_kernel(const float* __restrict__ table,
                            const int*   __restrict__ ridx) {
    int nm = blockIdx.x * blockDim.x + threadIdx.x;
    if (nm >= NTOK * NTOK) return;
    int ri = ridx[nm];
    #pragma unroll
    for (int h = 0; h < NH; h++)
        g_bias[h * NTOK * NTOK + nm] = table[ri * NH + h];
}

// ---------------- tf32 NT GEMM (2-stage, 2 CTAs/SM): C = A*B^T + bias ----------
// QKV_MODE: pre-scale Q columns (col<256), round output. CVT_A: A is raw fp32.
#define GSS 36
#define GST (128 * GSS)
template<bool QKV_MODE, bool CVT_A>
__global__ __launch_bounds__(256, 2)
void gemm_tf32(const float* __restrict__ A, const float* __restrict__ B,
               const float* __restrict__ bias, float* __restrict__ C,
               int M, int N, int K)
{
    extern __shared__ float sm[];
    float* As = sm;               // 2 stages
    float* Bs = sm + 2 * GST;

    const int tid  = threadIdx.x;
    const int warp = tid >> 5, lane = tid & 31;
    const int qg   = lane >> 2, tg = lane & 3;
    const int wm   = (warp >> 2) * 64;
    const int wn   = (warp & 3) * 32;
    const int row0 = blockIdx.y * 128, col0 = blockIdx.x * 128;

    float c[4][4][4];
    #pragma unroll
    for (int i = 0; i < 4; i++)
        #pragma unroll
        for (int j = 0; j < 4; j++)
            #pragma unroll
            for (int t = 0; t < 4; t++) c[i][j][t] = 0.0f;

    const int KT = K / 32;

    auto load_stage = [&](int stage, int k0) {
        #pragma unroll
        for (int i = 0; i < 4; i++) {
            int id = tid + i * 256;
            int r = id >> 3, c4 = (id & 7) * 4;
            cp16(As + stage * GST + r * GSS + c4,
                 A + (size_t)(row0 + r) * K + k0 + c4);
            cp16(Bs + stage * GST + r * GSS + c4,
                 B + (size_t)(col0 + r) * K + k0 + c4);
        }
        cp_commit();
    };

    load_stage(0, 0);

    for (int kt = 0; kt < KT; kt++) {
        if (kt + 1 < KT) {
            load_stage((kt + 1) & 1, (kt + 1) * 32);
            asm volatile("cp.async.wait_group 1;");
        } else {
            asm volatile("cp.async.wait_group 0;");
        }
        __syncthreads();

        const float* Asb = As + (kt & 1) * GST;
        const float* Bsb = Bs + (kt & 1) * GST;

        #pragma unroll
        for (int ks = 0; ks < 4; ks++) {
            int kk = ks * 8;
            uint32_t af[4][4], bf[4][2];
            #pragma unroll
            for (int i = 0; i < 4; i++) {
                const float* p = Asb + (wm + i * 16 + qg) * GSS + kk + tg;
                if (CVT_A) {
                    af[i][0] = f2tf32(p[0]);
                    af[i][1] = f2tf32(p[8 * GSS]);
                    af[i][2] = f2tf32(p[4]);
                    af[i][3] = f2tf32(p[8 * GSS + 4]);
                } else {
                    af[i][0] = lduf(p);
                    af[i][1] = lduf(p + 8 * GSS);
                    af[i][2] = lduf(p + 4);
                    af[i][3] = lduf(p + 8 * GSS + 4);
                }
            }
            #pragma unroll
            for (int j = 0; j < 4; j++) {
                const float* p = Bsb + (wn + j * 8 + qg) * GSS + kk + tg;
                bf[j][0] = lduf(p);
                bf[j][1] = lduf(p + 4);
            }
            #pragma unroll
            for (int i = 0; i < 4; i++)
                #pragma unroll
                for (int j = 0; j < 4; j++)
                    mma_tf32(c[i][j], af[i], bf[j]);
        }
        __syncthreads();
    }

    const float scale = 0.17677669529663687f;   // 32^-0.5
    #pragma unroll
    for (int i = 0; i < 4; i++) {
        int row = row0 + wm + i * 16 + qg;
        #pragma unroll
        for (int j = 0; j < 4; j++) {
            int col = col0 + wn + j * 8 + 2 * tg;
            float b0 = bias[col], b1 = bias[col + 1];
            float v00 = c[i][j][0] + b0, v01 = c[i][j][1] + b1;
            float v10 = c[i][j][2] + b0, v11 = c[i][j][3] + b1;
            if (QKV_MODE) {
                if (col < 256) { v00 *= scale; v01 *= scale; v10 *= scale; v11 *= scale; }
                v00 = tf32r(v00); v01 = tf32r(v01); v10 = tf32r(v10); v11 = tf32r(v11);
            }
            *(float2*)&C[(size_t)row * N + col]       = make_float2(v00, v01);
            *(float2*)&C[(size_t)(row + 8) * N + col] = make_float2(v10, v11);
        }
    }
}

// ---------------- tensor-core flash attention: CTA per (b,h), 2 CTAs/SM -------
// 32-key blocks; P tile aliases the Q smem region (Q lives in registers).
#define QS 36
#define KS 36
#define VS 40
#define PS 36
__global__ __launch_bounds__(256, 2)
void attn_mma(const float* __restrict__ mask)
{
    extern __shared__ float sm[];
    float* Qs = sm;                  // 256*36  (re-used as P after Q->regs)
    float* Ks = Qs + 256 * QS;       // 256*36
    float* Vs = Ks + 256 * KS;       // 256*40
    float* Ps = Qs;                  // alias: warp w uses rows [32w,32w+32)

    const int bh = blockIdx.x, b = bh >> 3, h = bh & 7;
    const int tid = threadIdx.x, warp = tid >> 5, lane = tid & 31;
    const int qg = lane >> 2, tg = lane & 3;

    // stage Q (already scaled+rounded), K, V via cp.async float4
    const float* base = g_qkv + (size_t)b * NTOK * QKVD + h * 32;
    #pragma unroll
    for (int id = tid; id < 2048; id += 256) {
        int m = id >> 3, c4 = (id & 7) * 4;
        const float* src = base + m * QKVD + c4;
        cp16(Qs + m * QS + c4, src);
        cp16(Ks + m * KS + c4, src + 256);
        cp16(Vs + m * VS + c4, src + 512);
    }
    cp_commit();
    asm volatile("cp.async.wait_group 0;");
    __syncthreads();

    const int wm = warp * 32;
    float* Pw = Ps + wm * PS;
    const float* bias_h = g_bias + (size_t)h * NTOK * NTOK;
    const float* mask_w = mask + (size_t)(b & 63) * NTOK * NTOK;

    // persistent Q fragments
    uint32_t qf[2][4][4];
    #pragma unroll
    for (int i = 0; i < 2; i++)
        #pragma unroll
        for (int kt = 0; kt < 4; kt++) {
            const float* p = Qs + (wm + 16 * i + qg) * QS + 8 * kt + tg;
            qf[i][kt][0] = lduf(p);
            qf[i][kt][1] = lduf(p + 8 * QS);
            qf[i][kt][2] = lduf(p + 4);
            qf[i][kt][3] = lduf(p + 8 * QS + 4);
        }
    __syncwarp();   // all lanes' Q frags read before P overwrites the region

    float O[2][4][4];
    #pragma unroll
    for (int i = 0; i < 2; i++)
        #pragma unroll
        for (int j = 0; j < 4; j++)
            #pragma unroll
            for (int t = 0; t < 4; t++) O[i][j][t] = 0.0f;
    float mrun[4] = {-1e30f, -1e30f, -1e30f, -1e30f};
    float lrun[4] = {0.f, 0.f, 0.f, 0.f};

    #pragma unroll 1
    for (int nb = 0; nb < 8; nb++) {
        const int n0 = nb * 32;

        // ---- init S with bias + mask
        float S[2][4][4];
        #pragma unroll
        for (int i = 0; i < 2; i++) {
            int row = wm + 16 * i + qg;
            #pragma unroll
            for (int j = 0; j < 4; j++) {
                int col = n0 + 8 * j + 2 * tg;
                float2 b0 = *(const float2*)(bias_h + (size_t)row * NTOK + col);
                float2 m0 = *(const float2*)(mask_w + (size_t)row * NTOK + col);
                float2 b1 = *(const float2*)(bias_h + (size_t)(row + 8) * NTOK + col);
                float2 m1 = *(const float2*)(mask_w + (size_t)(row + 8) * NTOK + col);
                S[i][j][0] = b0.x + m0.x;
                S[i][j][1] = b0.y + m0.y;
                S[i][j][2] = b1.x + m1.x;
                S[i][j][3] = b1.y + m1.y;
            }
        }

        // ---- S += Q K^T (32 keys)
        #pragma unroll
        for (int kt = 0; kt < 4; kt++) {
            #pragma unroll
            for (int j = 0; j < 4; j++) {
                uint32_t bf[2];
                const float* p = Ks + (n0 + 8 * j + qg) * KS + 8 * kt + tg;
                bf[0] = lduf(p);
                bf[1] = lduf(p + 4);
                mma_tf32(S[0][j], qf[0][kt], bf);
                mma_tf32(S[1][j], qf[1][kt], bf);
            }
        }

        // ---- online softmax (4 rows/thread), rounded P to smem
        #pragma unroll
        for (int i = 0; i < 2; i++)
            #pragma unroll
            for (int e = 0; e < 2; e++) {
                const int r = 2 * i + e;
                float mx = fmaxf(fmaxf(S[i][0][2 * e], S[i][0][2 * e + 1]),
                                 fmaxf(S[i][1][2 * e], S[i][1][2 * e + 1]));
                mx = fmaxf(mx, fmaxf(fmaxf(S[i][2][2 * e], S[i][2][2 * e + 1]),
                                     fmaxf(S[i][3][2 * e], S[i][3][2 * e + 1])));
                mx = fmaxf(mx, __shfl_xor_sync(0xffffffffu, mx, 1));
                mx = fmaxf(mx, __shfl_xor_sync(0xffffffffu, mx, 2));

                float mnew = fmaxf(mrun[r], mx);
                float cor = __expf(mrun[r] - mnew);
                lrun[r] *= cor;
                #pragma unroll
                for (int j = 0; j < 4; j++) {
                    O[i][j][2 * e]     *= cor;
                    O[i][j][2 * e + 1] *= cor;
                }
                mrun[r] = mnew;

                float psum = 0.0f;
                float* prow = Pw + (16 * i + qg + 8 * e) * PS + 2 * tg;
                #pragma unroll
                for (int j = 0; j < 4; j++) {
                    float p0 = __expf(S[i][j][2 * e]     - mnew);
                    float p1 = __expf(S[i][j][2 * e + 1] - mnew);
                    psum += p0 + p1;
                    *(float2*)(prow + 8 * j) = make_float2(tf32r(p0), tf32r(p1));
                }
                psum += __shfl_xor_sync(0xffffffffu, psum, 1);
                psum += __shfl_xor_sync(0xffffffffu, psum, 2);
                lrun[r] += psum;
            }
        __syncwarp();

        // ---- O += P V (32 keys = 4 k-tiles)
        #pragma unroll
        for (int ks = 0; ks < 4; ks++) {
            uint32_t af[2][4];
            #pragma unroll
            for (int i = 0; i < 2; i++) {
                const float* p = Pw + (16 * i + qg) * PS + 8 * ks + tg;
                af[i][0] = lduf(p);
                af[i][1] = lduf(p + 8 * PS);
                af[i][2] = lduf(p + 4);
                af[i][3] = lduf(p + 8 * PS + 4);
            }
            #pragma unroll
            for (int j = 0; j < 4; j++) {
                uint32_t bf[2];
                const float* p = Vs + (n0 + 8 * ks + tg) * VS + 8 * j + qg;
                bf[0] = lduf(p);
                bf[1] = lduf(p + 4 * VS);
                mma_tf32(O[0][j], af[0], bf);
                mma_tf32(O[1][j], af[1], bf);
            }
        }
        __syncwarp();
    }

    float inv[4];
    #pragma unroll
    for (int r = 0; r < 4; r++) inv[r] = 1.0f / lrun[r];

    #pragma unroll
    for (int i = 0; i < 2; i++) {
        int row = wm + 16 * i + qg;
        #pragma unroll
        for (int j = 0; j < 4; j++) {
            int col = h * 32 + 8 * j + 2 * tg;
            *(float2*)&g_att[((size_t)b * NTOK + row) * CDIM + col] =
                make_float2(tf32r(O[i][j][0] * inv[2 * i]), tf32r(O[i][j][1] * inv[2 * i]));
            *(float2*)&g_att[((size_t)b * NTOK + row + 8) * CDIM + col] =
                make_float2(tf32r(O[i][j][2] * inv[2 * i + 1]), tf32r(O[i][j][3] * inv[2 * i + 1]));
        }
    }
}

// --------------------------------------------------------------------------
extern "C" void kernel_launch(void* const* d_in, const int* in_sizes, int n_in,
                              void* d_out, int out_size)
{
    const float* x      = (const float*)d_in[0];
    const float* mask   = (const float*)d_in[1];
    const float* qkv_w  = (const float*)d_in[2];
    const float* qkv_b  = (const float*)d_in[3];
    const float* proj_w = (const float*)d_in[4];
    const float* proj_b = (const float*)d_in[5];
    const float* table  = (const float*)d_in[6];
    const int*   ridx   = (const int*)d_in[7];
    float* out = (float*)d_out;

    float *qkv_ptr, *att_ptr, *wr_ptr;
    cudaGetSymbolAddress((void**)&qkv_ptr, g_qkv);
    cudaGetSymbolAddress((void**)&att_ptr, g_att);
    cudaGetSymbolAddress((void**)&wr_ptr,  g_wr);
    float* qkvw_r  = wr_ptr;
    float* projw_r = wr_ptr + QKVD * CDIM;

    const int gemm_smem = 2 * 2 * GST * 4;                       // 73728 B
    const int attn_smem = (256 * QS + 256 * KS + 256 * VS) * 4;  // 114688 B
    cudaFuncSetAttribute((const void*)gemm_tf32<true, true>,
                         cudaFuncAttributeMaxDynamicSharedMemorySize, gemm_smem);
    cudaFuncSetAttribute((const void*)gemm_tf32<false, false>,
                         cudaFuncAttributeMaxDynamicSharedMemorySize, gemm_smem);
    cudaFuncSetAttribute((const void*)attn_mma,
                         cudaFuncAttributeMaxDynamicSharedMemorySize, attn_smem);

    // 0) prep: round weights to tf32 (RNA); x is cvt'd in-kernel
    round_kernel<<<(QKVD * CDIM / 4 + 255) / 256, 256>>>((const float4*)qkv_w, (float4*)qkvw_r, QKVD * CDIM / 4);
    round_kernel<<<(CDIM * CDIM / 4 + 255) / 256, 256>>>((const float4*)proj_w, (float4*)projw_r, CDIM * CDIM / 4);

    // 1) rel-pos bias gather
    bias_kernel<<<(NTOK * NTOK + 255) / 256, 256>>>(table, ridx);

    // 2) QKV projection (rounded output, Q pre-scaled)
    gemm_tf32<true, true><<<dim3(QKVD / 128, (NBATCH * NTOK) / 128), 256, gemm_smem>>>(
        x, qkvw_r, qkv_b, qkv_ptr, NBATCH * NTOK, QKVD, CDIM);

    // 3) window attention (tensor-core flash)
    attn_mma<<<NBATCH * NH, 256, attn_smem>>>(mask);

    // 4) output projection
    gemm_tf32<false, false><<<dim3(CDIM / 128, (NBATCH * NTOK) / 128), 256, gemm_smem>>>(
        att_ptr, projw_r, proj_b, out, NBATCH * NTOK, CDIM, CDIM);
}

// round 6
// speedup vs baseline: 4.6479x; 1.0370x over previous
#include <cuda_runtime.h>
#include <math.h>
#include <stdint.h>

#define NBATCH 192
#define NTOK   256
#define CDIM   256
#define NH     8
#define HD     32
#define QKVD   768   // 3*C

// ---------------- scratch (static __device__, no runtime alloc) ----------------
__device__ float g_qkv [NBATCH * NTOK * QKVD];   // (B, N, 3*H*hd), tf32-rounded, Q pre-scaled
__device__ float g_bias[NH * NTOK * NTOK];       // (H, N, N)
__device__ float g_att [NBATCH * NTOK * CDIM];   // attention out, tf32-rounded
__device__ float g_wr  [QKVD * CDIM + CDIM * CDIM]; // rounded qkv_w | proj_w

// ---------------- helpers ----------------
__device__ __forceinline__ uint32_t f2tf32(float f) {
    uint32_t r;
    asm("cvt.rna.tf32.f32 %0, %1;" : "=r"(r) : "f"(f));
    return r;
}
__device__ __forceinline__ float tf32r(float f) { return __uint_as_float(f2tf32(f)); }
__device__ __forceinline__ void cp16(void* smemp, const void* g) {
    uint32_t s = (uint32_t)__cvta_generic_to_shared(smemp);
    asm volatile("cp.async.cg.shared.global [%0], [%1], 16;" :: "r"(s), "l"(g));
}
__device__ __forceinline__ void cp_commit() { asm volatile("cp.async.commit_group;"); }
__device__ __forceinline__ void mma_tf32(float c[4], const uint32_t a[4], const uint32_t b[2]) {
    asm volatile(
        "mma.sync.aligned.m16n8k8.row.col.f32.tf32.tf32.f32 "
        "{%0,%1,%2,%3}, {%4,%5,%6,%7}, {%8,%9}, {%0,%1,%2,%3};"
        : "+f"(c[0]), "+f"(c[1]), "+f"(c[2]), "+f"(c[3])
        : "r"(a[0]), "r"(a[1]), "r"(a[2]), "r"(a[3]), "r"(b[0]), "r"(b[1]));
}
__device__ __forceinline__ uint32_t fbits(float f) { return __float_as_uint(f); }

// ---------------- prep: round a buffer to tf32 (RNA) ----------------
__global__ void round_kernel(const float4* __restrict__ in, float4* __restrict__ out, int n4) {
    int i = blockIdx.x * blockDim.x + threadIdx.x;
    if (i >= n4) return;
    float4 v = in[i];
    v.x = tf32r(v.x); v.y = tf32r(v.y); v.z = tf32r(v.z); v.w = tf32r(v.w);
    out[i] = v;
}

// ---------------- rel-pos bias gather ----------------
__global__ void bias_kernel(const float* __restrict__ table,
                            const int*   __restrict__ ridx) {
    int nm = blockIdx.x * blockDim.x + threadIdx.x;
    if (nm >= NTOK * NTOK) return;
    int ri = ridx[nm];
    #pragma unroll
    for (int h = 0; h < NH; h++)
        g_bias[h * NTOK * NTOK + nm] = table[ri * NH + h];
}

// ---------------- tf32 NT GEMM (2-stage, 2 CTAs/SM): C = A*B^T + bias ----------
// k-permuted fragments: slot(tg,s) holds physical k = 2*tg+s for BOTH A and B,
// so every fragment load is one float2 LDS.64. Stride 40 (== 8 mod 32) -> CF.
#define GSS 40
#define GST (128 * GSS)
template<bool QKV_MODE, bool CVT_A>
__global__ __launch_bounds__(256, 2)
void gemm_tf32(const float* __restrict__ A, const float* __restrict__ B,
               const float* __restrict__ bias, float* __restrict__ C,
               int M, int N, int K)
{
    extern __shared__ float sm[];
    float* As = sm;               // 2 stages
    float* Bs = sm + 2 * GST;

    const int tid  = threadIdx.x;
    const int warp = tid >> 5, lane = tid & 31;
    const int qg   = lane >> 2, tg = lane & 3;
    const int wm   = (warp >> 2) * 64;
    const int wn   = (warp & 3) * 32;
    const int row0 = blockIdx.y * 128, col0 = blockIdx.x * 128;

    float c[4][4][4];
    #pragma unroll
    for (int i = 0; i < 4; i++)
        #pragma unroll
        for (int j = 0; j < 4; j++)
            #pragma unroll
            for (int t = 0; t < 4; t++) c[i][j][t] = 0.0f;

    const int KT = K / 32;

    auto load_stage = [&](int stage, int k0) {
        #pragma unroll
        for (int i = 0; i < 4; i++) {
            int id = tid + i * 256;
            int r = id >> 3, c4 = (id & 7) * 4;
            cp16(As + stage * GST + r * GSS + c4,
                 A + (size_t)(row0 + r) * K + k0 + c4);
            cp16(Bs + stage * GST + r * GSS + c4,
                 B + (size_t)(col0 + r) * K + k0 + c4);
        }
        cp_commit();
    };

    load_stage(0, 0);

    for (int kt = 0; kt < KT; kt++) {
        if (kt + 1 < KT) {
            load_stage((kt + 1) & 1, (kt + 1) * 32);
            asm volatile("cp.async.wait_group 1;");
        } else {
            asm volatile("cp.async.wait_group 0;");
        }
        __syncthreads();

        const float* Asb = As + (kt & 1) * GST;
        const float* Bsb = Bs + (kt & 1) * GST;

        #pragma unroll
        for (int ks = 0; ks < 4; ks++) {
            int kk = ks * 8 + 2 * tg;
            uint32_t af[4][4], bf[4][2];
            #pragma unroll
            for (int i = 0; i < 4; i++) {
                const float* p = Asb + (wm + i * 16 + qg) * GSS + kk;
                float2 v0 = *(const float2*)p;
                float2 v1 = *(const float2*)(p + 8 * GSS);
                if (CVT_A) {
                    af[i][0] = f2tf32(v0.x); af[i][2] = f2tf32(v0.y);
                    af[i][1] = f2tf32(v1.x); af[i][3] = f2tf32(v1.y);
                } else {
                    af[i][0] = fbits(v0.x);  af[i][2] = fbits(v0.y);
                    af[i][1] = fbits(v1.x);  af[i][3] = fbits(v1.y);
                }
            }
            #pragma unroll
            for (int j = 0; j < 4; j++) {
                float2 v = *(const float2*)(Bsb + (wn + j * 8 + qg) * GSS + kk);
                bf[j][0] = fbits(v.x);
                bf[j][1] = fbits(v.y);
            }
            #pragma unroll
            for (int i = 0; i < 4; i++)
                #pragma unroll
                for (int j = 0; j < 4; j++)
                    mma_tf32(c[i][j], af[i], bf[j]);
        }
        __syncthreads();
    }

    const float scale = 0.17677669529663687f;   // 32^-0.5
    #pragma unroll
    for (int i = 0; i < 4; i++) {
        int row = row0 + wm + i * 16 + qg;
        #pragma unroll
        for (int j = 0; j < 4; j++) {
            int col = col0 + wn + j * 8 + 2 * tg;
            float b0 = bias[col], b1 = bias[col + 1];
            float v00 = c[i][j][0] + b0, v01 = c[i][j][1] + b1;
            float v10 = c[i][j][2] + b0, v11 = c[i][j][3] + b1;
            if (QKV_MODE) {
                if (col < 256) { v00 *= scale; v01 *= scale; v10 *= scale; v11 *= scale; }
                v00 = tf32r(v00); v01 = tf32r(v01); v10 = tf32r(v10); v11 = tf32r(v11);
            }
            *(float2*)&C[(size_t)row * N + col]       = make_float2(v00, v01);
            *(float2*)&C[(size_t)(row + 8) * N + col] = make_float2(v10, v11);
        }
    }
}

// ---------------- tensor-core flash attention: CTA per (b,h), 2 CTAs/SM -------
// Q frags direct from global; K stride 40 (float2 frags CF); V stride 36;
// compact per-warp 32x32 P tile with XOR swizzle on the 8-col block.
#define KS2 40
#define VS2 36
__global__ __launch_bounds__(256, 2)
void attn_mma(const float* __restrict__ mask)
{
    extern __shared__ float sm[];
    float* Ks = sm;                   // 256*40
    float* Vs = Ks + 256 * KS2;       // 256*36
    float* Ps = Vs + 256 * VS2;       // 8 warps * 32*32

    const int bh = blockIdx.x, b = bh >> 3, h = bh & 7;
    const int tid = threadIdx.x, warp = tid >> 5, lane = tid & 31;
    const int qg = lane >> 2, tg = lane & 3;

    // stage K, V via cp.async float4
    const float* base = g_qkv + (size_t)b * NTOK * QKVD + h * 32;
    #pragma unroll
    for (int id = tid; id < 2048; id += 256) {
        int m = id >> 3, c4 = (id & 7) * 4;
        const float* src = base + m * QKVD + c4;
        cp16(Ks + m * KS2 + c4, src + 256);
        cp16(Vs + m * VS2 + c4, src + 512);
    }
    cp_commit();

    const int wm = warp * 32;
    float* Pw = Ps + warp * 1024;
    const float* bias_h = g_bias + (size_t)h * NTOK * NTOK;
    const float* mask_w = mask + (size_t)(b & 63) * NTOK * NTOK;

    // persistent Q fragments, straight from global (tf32-rounded, pre-scaled)
    uint32_t qf[2][4][4];
    #pragma unroll
    for (int i = 0; i < 2; i++)
        #pragma unroll
        for (int kt = 0; kt < 4; kt++) {
            const float* p = base + (size_t)(wm + 16 * i + qg) * QKVD + 8 * kt + 2 * tg;
            float2 v0 = *(const float2*)p;
            float2 v1 = *(const float2*)(p + 8 * QKVD);
            qf[i][kt][0] = fbits(v0.x); qf[i][kt][2] = fbits(v0.y);
            qf[i][kt][1] = fbits(v1.x); qf[i][kt][3] = fbits(v1.y);
        }

    float O[2][4][4];
    #pragma unroll
    for (int i = 0; i < 2; i++)
        #pragma unroll
        for (int j = 0; j < 4; j++)
            #pragma unroll
            for (int t = 0; t < 4; t++) O[i][j][t] = 0.0f;
    float mrun[4] = {-1e30f, -1e30f, -1e30f, -1e30f};
    float lrun[4] = {0.f, 0.f, 0.f, 0.f};

    asm volatile("cp.async.wait_group 0;");
    __syncthreads();

    #pragma unroll 1
    for (int nb = 0; nb < 8; nb++) {
        const int n0 = nb * 32;

        // ---- init S with bias + mask
        float S[2][4][4];
        #pragma unroll
        for (int i = 0; i < 2; i++) {
            int row = wm + 16 * i + qg;
            #pragma unroll
            for (int j = 0; j < 4; j++) {
                int col = n0 + 8 * j + 2 * tg;
                float2 b0 = *(const float2*)(bias_h + (size_t)row * NTOK + col);
                float2 m0 = *(const float2*)(mask_w + (size_t)row * NTOK + col);
                float2 b1 = *(const float2*)(bias_h + (size_t)(row + 8) * NTOK + col);
                float2 m1 = *(const float2*)(mask_w + (size_t)(row + 8) * NTOK + col);
                S[i][j][0] = b0.x + m0.x;
                S[i][j][1] = b0.y + m0.y;
                S[i][j][2] = b1.x + m1.x;
                S[i][j][3] = b1.y + m1.y;
            }
        }

        // ---- S += Q K^T (32 keys), k-permuted float2 K frags
        #pragma unroll
        for (int kt = 0; kt < 4; kt++) {
            #pragma unroll
            for (int j = 0; j < 4; j++) {
                float2 kv = *(const float2*)(Ks + (n0 + 8 * j + qg) * KS2 + 8 * kt + 2 * tg);
                uint32_t bf[2] = { fbits(kv.x), fbits(kv.y) };
                mma_tf32(S[0][j], qf[0][kt], bf);
                mma_tf32(S[1][j], qf[1][kt], bf);
            }
        }

        // ---- online softmax (4 rows/thread), rounded P to swizzled smem
        #pragma unroll
        for (int i = 0; i < 2; i++)
            #pragma unroll
            for (int e = 0; e < 2; e++) {
                const int r = 2 * i + e;
                float mx = fmaxf(fmaxf(S[i][0][2 * e], S[i][0][2 * e + 1]),
                                 fmaxf(S[i][1][2 * e], S[i][1][2 * e + 1]));
                mx = fmaxf(mx, fmaxf(fmaxf(S[i][2][2 * e], S[i][2][2 * e + 1]),
                                     fmaxf(S[i][3][2 * e], S[i][3][2 * e + 1])));
                mx = fmaxf(mx, __shfl_xor_sync(0xffffffffu, mx, 1));
                mx = fmaxf(mx, __shfl_xor_sync(0xffffffffu, mx, 2));

                float mnew = fmaxf(mrun[r], mx);
                float cor = __expf(mrun[r] - mnew);
                lrun[r] *= cor;
                #pragma unroll
                for (int j = 0; j < 4; j++) {
                    O[i][j][2 * e]     *= cor;
                    O[i][j][2 * e + 1] *= cor;
                }
                mrun[r] = mnew;

                float psum = 0.0f;
                const int prow = 16 * i + 8 * e + qg;        // local row 0..31
                float* pbase = Pw + prow * 32 + 2 * tg;
                const int sw = prow & 3;
                #pragma unroll
                for (int j = 0; j < 4; j++) {
                    float p0 = __expf(S[i][j][2 * e]     - mnew);
                    float p1 = __expf(S[i][j][2 * e + 1] - mnew);
                    psum += p0 + p1;
                    *(float2*)(pbase + 8 * (j ^ sw)) = make_float2(tf32r(p0), tf32r(p1));
                }
                psum += __shfl_xor_sync(0xffffffffu, psum, 1);
                psum += __shfl_xor_sync(0xffffffffu, psum, 2);
                lrun[r] += psum;
            }
        __syncwarp();

        // ---- O += P V (32 keys = 4 k-tiles), k-permuted
        #pragma unroll
        for (int ks = 0; ks < 4; ks++) {
            uint32_t af[2][4];
            #pragma unroll
            for (int i = 0; i < 2; i++) {
                const int r0 = 16 * i + qg;                  // rows r0, r0+8 (same &3)
                const int sw = r0 & 3;
                float2 v0 = *(const float2*)(Pw + r0 * 32       + 8 * (ks ^ sw) + 2 * tg);
                float2 v1 = *(const float2*)(Pw + (r0 + 8) * 32 + 8 * (ks ^ sw) + 2 * tg);
                af[i][0] = fbits(v0.x); af[i][2] = fbits(v0.y);
                af[i][1] = fbits(v1.x); af[i][3] = fbits(v1.y);
            }
            #pragma unroll
            for (int j = 0; j < 4; j++) {
                const float* p = Vs + (n0 + 8 * ks + 2 * tg) * VS2 + 8 * j + qg;
                uint32_t bf[2] = { fbits(p[0]), fbits(p[VS2]) };
                mma_tf32(O[0][j], af[0], bf);
                mma_tf32(O[1][j], af[1], bf);
            }
        }
        __syncwarp();
    }

    float inv[4];
    #pragma unroll
    for (int r = 0; r < 4; r++) inv[r] = 1.0f / lrun[r];

    #pragma unroll
    for (int i = 0; i < 2; i++) {
        int row = wm + 16 * i + qg;
        #pragma unroll
        for (int j = 0; j < 4; j++) {
            int col = h * 32 + 8 * j + 2 * tg;
            *(float2*)&g_att[((size_t)b * NTOK + row) * CDIM + col] =
                make_float2(tf32r(O[i][j][0] * inv[2 * i]), tf32r(O[i][j][1] * inv[2 * i]));
            *(float2*)&g_att[((size_t)b * NTOK + row + 8) * CDIM + col] =
                make_float2(tf32r(O[i][j][2] * inv[2 * i + 1]), tf32r(O[i][j][3] * inv[2 * i + 1]));
        }
    }
}

// --------------------------------------------------------------------------
extern "C" void kernel_launch(void* const* d_in, const int* in_sizes, int n_in,
                              void* d_out, int out_size)
{
    const float* x      = (const float*)d_in[0];
    const float* mask   = (const float*)d_in[1];
    const float* qkv_w  = (const float*)d_in[2];
    const float* qkv_b  = (const float*)d_in[3];
    const float* proj_w = (const float*)d_in[4];
    const float* proj_b = (const float*)d_in[5];
    const float* table  = (const float*)d_in[6];
    const int*   ridx   = (const int*)d_in[7];
    float* out = (float*)d_out;

    float *qkv_ptr, *att_ptr, *wr_ptr;
    cudaGetSymbolAddress((void**)&qkv_ptr, g_qkv);
    cudaGetSymbolAddress((void**)&att_ptr, g_att);
    cudaGetSymbolAddress((void**)&wr_ptr,  g_wr);
    float* qkvw_r  = wr_ptr;
    float* projw_r = wr_ptr + QKVD * CDIM;

    const int gemm_smem = 2 * 2 * GST * 4;                             // 81920 B
    const int attn_smem = (256 * KS2 + 256 * VS2 + 8 * 1024) * 4;      // 110592 B
    cudaFuncSetAttribute((const void*)gemm_tf32<true, true>,
                         cudaFuncAttributeMaxDynamicSharedMemorySize, gemm_smem);
    cudaFuncSetAttribute((const void*)gemm_tf32<false, false>,
                         cudaFuncAttributeMaxDynamicSharedMemorySize, gemm_smem);
    cudaFuncSetAttribute((const void*)attn_mma,
                         cudaFuncAttributeMaxDynamicSharedMemorySize, attn_smem);

    // 0) prep: round weights to tf32 (RNA); x is cvt'd in-kernel
    round_kernel<<<(QKVD * CDIM / 4 + 255) / 256, 256>>>((const float4*)qkv_w, (float4*)qkvw_r, QKVD * CDIM / 4);
    round_kernel<<<(CDIM * CDIM / 4 + 255) / 256, 256>>>((const float4*)proj_w, (float4*)projw_r, CDIM * CDIM / 4);

    // 1) rel-pos bias gather
    bias_kernel<<<(NTOK * NTOK + 255) / 256, 256>>>(table, ridx);

    // 2) QKV projection (rounded output, Q pre-scaled)
    gemm_tf32<true, true><<<dim3(QKVD / 128, (NBATCH * NTOK) / 128), 256, gemm_smem>>>(
        x, qkvw_r, qkv_b, qkv_ptr, NBATCH * NTOK, QKVD, CDIM);

    // 3) window attention (tensor-core flash)
    attn_mma<<<NBATCH * NH, 256, attn_smem>>>(mask);

    // 4) output projection
    gemm_tf32<false, false><<<dim3(CDIM / 128, (NBATCH * NTOK) / 128), 256, gemm_smem>>>(
        att_ptr, projw_r, proj_b, out, NBATCH * NTOK, CDIM, CDIM);
}